// round 10
// baseline (speedup 1.0000x reference)
#include <cuda_runtime.h>
#include <cstdint>

#define BATCH 8
#define CH    256
#define HH    96
#define WW    96
#define HW    (HH*WW)
#define DMAX  4
#define DD    9
#define NSH   81
#define TILE_W 32
#define TILE_H 8
#define NTHR  192                       // (8,8,3)
#define CC    4
#define NCHUNK (CH/CC)                  // 64
#define NGRP  (NCHUNK/2)                // 32 pairs
#define HALO_H 16
#define HALO_W 40
#define HALO_WP 42                      // conflict-free stride for LDS.64 (42 mod 32 = 10)
#define F1_WORDS (CC*HALO_H*HALO_WP)    // 2688
#define F0_WORDS (CC*TILE_H*TILE_W)     // 1024
#define BUF_WORDS (F1_WORDS+F0_WORDS)   // 3712
#define NBUF 6
#define SMEM_BYTES (NBUF*BUF_WORDS*4)   // 89088 B per CTA (dynamic)
#define NF8 (CC*HALO_H*(HALO_W/2))      // 1280 8B copies -> 6 + 1 predicated per thread
#define NF16_F0 (F0_WORDS/4)            // 256 16B copies

typedef unsigned long long u64;

__device__ __forceinline__ void cp8(uint32_t dst, const void* src, int sz) {
    asm volatile("cp.async.ca.shared.global [%0], [%1], 8, %2;\n"
                 :: "r"(dst), "l"(src), "r"(sz));
}
__device__ __forceinline__ void cp16(uint32_t dst, const void* src) {
    asm volatile("cp.async.cg.shared.global [%0], [%1], 16;\n"
                 :: "r"(dst), "l"(src));
}
__device__ __forceinline__ void ffma2(u64& acc, u64 a, u64 b) {
    asm("fma.rn.f32x2 %0, %1, %2, %3;" : "=l"(acc) : "l"(a), "l"(b), "l"(acc));
}
__device__ __forceinline__ u64 pack2(float x, float y) {
    u64 d; asm("mov.b64 %0, {%1, %2};" : "=l"(d) : "f"(x), "f"(y)); return d;
}
__device__ __forceinline__ void unpack2(u64 d, float& x, float& y) {
    asm("mov.b64 {%0, %1}, %2;" : "=f"(x), "=f"(y) : "l"(d));
}
__device__ __forceinline__ float lo32(u64 d) { float x,y; unpack2(d,x,y); return x; }
__device__ __forceinline__ float hi32(u64 d) { float x,y; unpack2(d,x,y); return y; }

__global__ __launch_bounds__(NTHR, 2)
void corr_kernel(const float* __restrict__ FM0,
                 const float* __restrict__ FM1,
                 float* __restrict__ out)
{
    extern __shared__ float smem[];     // NBUF * BUF_WORDS = 89088 B

    const int tx  = threadIdx.x;          // 0..7  : 4 pixels each
    const int ty  = threadIdx.y;          // 0..7  : pixel row
    const int tz  = threadIdx.z;          // 0..2  : shift-row group (di = 3tz..3tz+2)
    const int tid = (tz * TILE_H + ty) * 8 + tx;
    const int w0  = blockIdx.x * TILE_W;
    const int h0  = blockIdx.y * TILE_H;
    const int b   = blockIdx.z;

    // ---- FM1 halo gather table: 6 + 1 predicated 8B cp.async per thread ----
    int dstw[7], srcw[7];
#pragma unroll
    for (int j = 0; j < 7; j++) {
        int idx = tid + NTHR * j;             // valid iff < 1280
        int cc  = idx / (HALO_H * (HALO_W/2));
        int rem = idx - cc * (HALO_H * (HALO_W/2));
        int r   = rem / (HALO_W/2);
        int c8  = rem - r * (HALO_W/2);
        dstw[j] = (cc * HALO_H + r) * HALO_WP + 2 * c8;
        int gh = h0 - DMAX + r;
        int gw = w0 - DMAX + 2 * c8;          // 2-aligned: fully in or out of [0,96)
        srcw[j] = ((unsigned)gh < HH && (unsigned)gw < WW)
                    ? cc * HW + gh * WW + gw : -1;
    }
    const bool f1v6 = (tid < NF8 - 6 * NTHR); // tid < 128

    // ---- FM0 stage mapping: 16B copies (256 total; threads 0..63 do two) ----
    const float* f0base = FM0 + (size_t)b * CH * HW;
    int f0dst[2]; size_t f0off[2];
#pragma unroll
    for (int j = 0; j < 2; j++) {
        int idx = tid + NTHR * j;             // valid iff < 256
        int cc  = idx >> 6;
        int rem = idx & 63;
        int row = rem >> 3;
        int c4  = rem & 7;
        f0dst[j] = F1_WORDS + (cc * TILE_H + row) * TILE_W + 4 * c4;
        f0off[j] = (size_t)cc * HW + (size_t)(h0 + row) * WW + w0 + 4 * c4;
    }
    const bool f0v1 = (tid < NF16_F0 - NTHR); // tid < 64

    const float* f1b = FM1 + (size_t)b * CH * HW;
    const uint32_t sbase = (uint32_t)__cvta_generic_to_shared(smem);

    auto issue = [&](int c0, int buf) {
        uint32_t base = sbase + (uint32_t)(buf * BUF_WORDS) * 4u;
#pragma unroll
        for (int j = 0; j < 7; j++) {
            if (j < 6 || f1v6) {
                int sw = srcw[j];
                const float* s = f1b + (size_t)c0 * HW + (sw < 0 ? 0 : sw);
                cp8(base + (uint32_t)dstw[j] * 4u, s, sw < 0 ? 0 : 8);
            }
        }
        cp16(base + (uint32_t)f0dst[0] * 4u, f0base + f0off[0] + (size_t)c0 * HW);
        if (f0v1)
            cp16(base + (uint32_t)f0dst[1] * 4u, f0base + f0off[1] + (size_t)c0 * HW);
        asm volatile("cp.async.commit_group;\n" ::: "memory");
    };

    // Accumulators: P[r][px][pair], S[r][px]  (3 rows x 4 px x (4 f32x2 + 1 scalar))
    u64   P[3][4][4];
    float S[3][4];
#pragma unroll
    for (int r = 0; r < 3; r++) {
#pragma unroll
        for (int i = 0; i < 4; i++) {
            S[r][i] = 0.f;
#pragma unroll
            for (int p = 0; p < 4; p++) P[r][i][p] = 0ull;
        }
    }

    auto compute = [&](int buf) {
        const float* sb = &smem[buf * BUF_WORDS];
#pragma unroll
        for (int cc = 0; cc < CC; cc++) {
            float4 f0 = *(const float4*)(sb + F1_WORDS +
                                         (cc * TILE_H + ty) * TILE_W + 4 * tx);
            const u64 fa0 = pack2(f0.x, f0.x);
            const u64 fa1 = pack2(f0.y, f0.y);
            const u64 fa2 = pack2(f0.z, f0.z);
            const u64 fa3 = pack2(f0.w, f0.w);
            const float* rp = sb + (cc * HALO_H + ty + 3 * tz) * HALO_WP + 4 * tx;
#pragma unroll
            for (int r = 0; r < 3; r++) {
                const u64* sp = (const u64*)(rp + r * HALO_WP);
                u64 v0 = sp[0], v1 = sp[1], v2 = sp[2],
                    v3 = sp[3], v4 = sp[4], v5 = sp[5];
                // px0 (cols 4tx+0..8): pairs v0..v3, scalar dj8 = v4.lo
                ffma2(P[r][0][0], fa0, v0); ffma2(P[r][0][1], fa0, v1);
                ffma2(P[r][0][2], fa0, v2); ffma2(P[r][0][3], fa0, v3);
                S[r][0] = fmaf(f0.x, lo32(v4), S[r][0]);
                // px1 (cols 4tx+1..9): scalar dj0 = v0.hi, pairs v1..v4
                ffma2(P[r][1][0], fa1, v1); ffma2(P[r][1][1], fa1, v2);
                ffma2(P[r][1][2], fa1, v3); ffma2(P[r][1][3], fa1, v4);
                S[r][1] = fmaf(f0.y, hi32(v0), S[r][1]);
                // px2 (cols 4tx+2..10): pairs v1..v4, scalar dj8 = v5.lo
                ffma2(P[r][2][0], fa2, v1); ffma2(P[r][2][1], fa2, v2);
                ffma2(P[r][2][2], fa2, v3); ffma2(P[r][2][3], fa2, v4);
                S[r][2] = fmaf(f0.z, lo32(v5), S[r][2]);
                // px3 (cols 4tx+3..11): scalar dj0 = v1.hi, pairs v2..v5
                ffma2(P[r][3][0], fa3, v2); ffma2(P[r][3][1], fa3, v3);
                ffma2(P[r][3][2], fa3, v4); ffma2(P[r][3][3], fa3, v5);
                S[r][3] = fmaf(f0.w, hi32(v1), S[r][3]);
            }
        }
    };

    // ---- prologue: stage chunks 0..3 into bufs 0..3 ----
    issue(0 * CC, 0);
    issue(1 * CC, 1);
    issue(2 * CC, 2);
    issue(3 * CC, 3);

    int cur = 0;                          // buf of first chunk of current pair
#pragma unroll 1
    for (int g = 0; g < NGRP; g++) {
        // chunks 2g, 2g+1 must be complete; 2g+2, 2g+3 may still be in flight
        if (g < NGRP - 1)
            asm volatile("cp.async.wait_group 2;\n" ::: "memory");
        else
            asm volatile("cp.async.wait_group 0;\n" ::: "memory");
        __syncthreads();   // also: everyone finished reading pair g-1's bufs

        // issue pair g+2 into the bufs pair g-1 just vacated
        if (g + 2 < NGRP) {
            int nb = cur + 4; if (nb >= NBUF) nb -= NBUF;
            issue((2 * g + 4) * CC, nb);
            nb = cur + 5; if (nb >= NBUF) nb -= NBUF;
            issue((2 * g + 5) * CC, nb);
        }

        compute(cur);
        int b1 = cur + 1; if (b1 >= NBUF) b1 -= NBUF;
        compute(b1);

        cur += 2; if (cur >= NBUF) cur -= NBUF;
    }

    // ---- coalesced output: 4 tile-rows per staging pass (2 passes) ----
#pragma unroll 1
    for (int g = 0; g < 2; g++) {
        __syncthreads();   // pass 0: all compute reads done; pass 1: all copies done
        if ((ty >> 2) == g) {
            float* st = &smem[(size_t)((ty & 3) * TILE_W + 4 * tx) * NSH];
#pragma unroll
            for (int r = 0; r < 3; r++) {
                const int base = (3 * tz + r) * DD;
                float x, y;
#pragma unroll
                for (int p = 0; p < 4; p++) {
                    unpack2(P[r][0][p], x, y);
                    st[0 * NSH + base + 2 * p]     = x;
                    st[0 * NSH + base + 2 * p + 1] = y;
                    unpack2(P[r][1][p], x, y);
                    st[1 * NSH + base + 2 * p + 1] = x;
                    st[1 * NSH + base + 2 * p + 2] = y;
                    unpack2(P[r][2][p], x, y);
                    st[2 * NSH + base + 2 * p]     = x;
                    st[2 * NSH + base + 2 * p + 1] = y;
                    unpack2(P[r][3][p], x, y);
                    st[3 * NSH + base + 2 * p + 1] = x;
                    st[3 * NSH + base + 2 * p + 2] = y;
                }
                st[0 * NSH + base + 8] = S[r][0];
                st[1 * NSH + base + 0] = S[r][1];
                st[2 * NSH + base + 8] = S[r][2];
                st[3 * NSH + base + 0] = S[r][3];
            }
        }
        __syncthreads();
        // copy 4 rows (10368 words) to gmem; out rows stride WW*NSH
        const float4* src = (const float4*)smem;
        for (int i = tid; i < 4 * TILE_W * NSH / 4; i += NTHR) {
            int row = i / (TILE_W * NSH / 4);            // 0..3
            int rem = i - row * (TILE_W * NSH / 4);
            float4* dst = (float4*)(out +
                ((size_t)(b * HH + h0 + 4 * g + row) * WW + w0) * NSH);
            dst[rem] = src[i];
        }
    }
}

extern "C" void kernel_launch(void* const* d_in, const int* in_sizes, int n_in,
                              void* d_out, int out_size)
{
    const float* FM0 = (const float*)d_in[0];
    const float* FM1 = (const float*)d_in[1];
    float* out = (float*)d_out;

    // Idempotent, host-side (capture-safe): 89 KB dynamic smem per CTA.
    cudaFuncSetAttribute(corr_kernel,
                         cudaFuncAttributeMaxDynamicSharedMemorySize, SMEM_BYTES);

    dim3 grid(WW / TILE_W, HH / TILE_H, BATCH);  // (3,12,8) = 288 blocks, 2 CTAs/SM, one wave
    dim3 block(8, TILE_H, 3);                     // 192 threads
    corr_kernel<<<grid, block, SMEM_BYTES>>>(FM0, FM1, out);
}

// round 11
// speedup vs baseline: 1.0425x; 1.0425x over previous
#include <cuda_runtime.h>
#include <cstdint>

#define BATCH 8
#define CH    256
#define HH    96
#define WW    96
#define HW    (HH*WW)
#define DMAX  4
#define DD    9
#define NSH   81
#define TILE_W 32
#define TILE_H 8
#define NTHR  192                       // (8,8,3)
#define CC    4
#define NCHUNK (CH/CC)                  // 64
#define HALO_H 16
#define HALO_W 40                       // no pad: pure LDS.128 phases are contiguous 128B rows
#define F1_WORDS (CC*HALO_H*HALO_W)     // 2560
#define F0_WORDS (CC*TILE_H*TILE_W)     // 1024
#define BUF_WORDS (F1_WORDS+F0_WORDS)   // 3584 -> 3 bufs = 43008 B static
#define NF16_F1 (F1_WORDS/4)            // 640 16B copies -> 3 + 1 predicated per thread
#define NF16_F0 (F0_WORDS/4)            // 256 16B copies

typedef unsigned long long u64;

__device__ __forceinline__ void cp16z(uint32_t dst, const void* src, int sz) {
    asm volatile("cp.async.cg.shared.global [%0], [%1], 16, %2;\n"
                 :: "r"(dst), "l"(src), "r"(sz));
}
__device__ __forceinline__ void cp16(uint32_t dst, const void* src) {
    asm volatile("cp.async.cg.shared.global [%0], [%1], 16;\n"
                 :: "r"(dst), "l"(src));
}
__device__ __forceinline__ void lds128(u64& a, u64& b, uint32_t addr) {
    asm volatile("ld.shared.v2.b64 {%0, %1}, [%2];"
                 : "=l"(a), "=l"(b) : "r"(addr));
}
__device__ __forceinline__ void ffma2(u64& acc, u64 a, u64 b) {
    asm("fma.rn.f32x2 %0, %1, %2, %3;" : "=l"(acc) : "l"(a), "l"(b), "l"(acc));
}
__device__ __forceinline__ u64 pack2(float x, float y) {
    u64 d; asm("mov.b64 %0, {%1, %2};" : "=l"(d) : "f"(x), "f"(y)); return d;
}
__device__ __forceinline__ void unpack2(u64 d, float& x, float& y) {
    asm("mov.b64 {%0, %1}, %2;" : "=f"(x), "=f"(y) : "l"(d));
}
__device__ __forceinline__ float lo32(u64 d) { float x,y; unpack2(d,x,y); return x; }
__device__ __forceinline__ float hi32(u64 d) { float x,y; unpack2(d,x,y); return y; }

__global__ __launch_bounds__(NTHR, 2)
void corr_kernel(const float* __restrict__ FM0,
                 const float* __restrict__ FM1,
                 float* __restrict__ out)
{
    __shared__ alignas(16) float smem[3 * BUF_WORDS];   // 43008 B

    const int tx  = threadIdx.x;          // 0..7  : 4 pixels each
    const int ty  = threadIdx.y;          // 0..7  : pixel row
    const int tz  = threadIdx.z;          // 0..2  : shift-row group (di = 3tz..3tz+2)
    const int tid = (tz * TILE_H + ty) * 8 + tx;
    const int w0  = blockIdx.x * TILE_W;
    const int h0  = blockIdx.y * TILE_H;
    const int b   = blockIdx.z;

    // ---- FM1 halo gather table: 3 + 1 predicated 16B cp.async per thread ----
    int dstw[4], srcw[4];
#pragma unroll
    for (int j = 0; j < 4; j++) {
        int idx = tid + NTHR * j;             // valid iff < 640
        int cc  = idx / (HALO_H * (HALO_W/4));
        int rem = idx - cc * (HALO_H * (HALO_W/4));
        int r   = rem / (HALO_W/4);
        int c4  = rem - r * (HALO_W/4);
        dstw[j] = (cc * HALO_H + r) * HALO_W + 4 * c4;
        int gh = h0 - DMAX + r;
        int gw = w0 - DMAX + 4 * c4;          // 4-aligned: fully in or out of [0,96)
        srcw[j] = ((unsigned)gh < HH && (unsigned)gw < WW)
                    ? cc * HW + gh * WW + gw : -1;
    }
    const bool f1v3 = (tid < NF16_F1 - 3 * NTHR); // tid < 64

    // ---- FM0 stage mapping: 16B copies (256 total; threads 0..63 do two) ----
    const float* f0base = FM0 + (size_t)b * CH * HW;
    int f0dst[2]; size_t f0off[2];
#pragma unroll
    for (int j = 0; j < 2; j++) {
        int idx = tid + NTHR * j;             // valid iff < 256
        int cc  = idx >> 6;
        int rem = idx & 63;
        int row = rem >> 3;
        int c4  = rem & 7;
        f0dst[j] = F1_WORDS + (cc * TILE_H + row) * TILE_W + 4 * c4;
        f0off[j] = (size_t)cc * HW + (size_t)(h0 + row) * WW + w0 + 4 * c4;
    }
    const bool f0v1 = (tid < NF16_F0 - NTHR); // tid < 64

    const float* f1b = FM1 + (size_t)b * CH * HW;
    const uint32_t sbase = (uint32_t)__cvta_generic_to_shared(smem);

    auto issue = [&](int c0, int buf) {
        uint32_t base = sbase + (uint32_t)(buf * BUF_WORDS) * 4u;
#pragma unroll
        for (int j = 0; j < 4; j++) {
            if (j < 3 || f1v3) {
                int sw = srcw[j];
                const float* s = f1b + (size_t)c0 * HW + (sw < 0 ? 0 : sw);
                cp16z(base + (uint32_t)dstw[j] * 4u, s, sw < 0 ? 0 : 16);
            }
        }
        cp16(base + (uint32_t)f0dst[0] * 4u, f0base + f0off[0] + (size_t)c0 * HW);
        if (f0v1)
            cp16(base + (uint32_t)f0dst[1] * 4u, f0base + f0off[1] + (size_t)c0 * HW);
        asm volatile("cp.async.commit_group;\n" ::: "memory");
    };

    // Accumulators: P[r][px][pair], S[r][px]  (3 rows x 4 px x (4 f32x2 + 1 scalar))
    u64   P[3][4][4];
    float S[3][4];
#pragma unroll
    for (int r = 0; r < 3; r++) {
#pragma unroll
        for (int i = 0; i < 4; i++) {
            S[r][i] = 0.f;
#pragma unroll
            for (int p = 0; p < 4; p++) P[r][i][p] = 0ull;
        }
    }

    // byte offset of this thread's row base within a buffer (add buf base + cc row)
    const uint32_t rowbyte0 = (uint32_t)(((ty + 3 * tz) * HALO_W + 4 * tx) * 4);

    issue(0, 0);
    issue(CC, 1);

    int cur = 0;                              // buffer holding chunk ci
#pragma unroll 1
    for (int ci = 0; ci < NCHUNK; ci++) {
        if (ci < NCHUNK - 1)
            asm volatile("cp.async.wait_group 1;\n" ::: "memory");
        else
            asm volatile("cp.async.wait_group 0;\n" ::: "memory");
        __syncthreads();      // chunk ci fully staged; all threads done computing ci-1

        // issue ci+2 into the buffer chunk ci-1 used (safe after the barrier)
        if (ci + 2 < NCHUNK) {
            int nb = cur + 2; if (nb >= 3) nb -= 3;
            issue((ci + 2) * CC, nb);
        }

        const float* sb = &smem[cur * BUF_WORDS];
        const uint32_t sboff = sbase + (uint32_t)(cur * BUF_WORDS) * 4u + rowbyte0;
#pragma unroll
        for (int cc = 0; cc < CC; cc++) {
            float4 f0 = *(const float4*)(sb + F1_WORDS +
                                         (cc * TILE_H + ty) * TILE_W + 4 * tx);
            const u64 fa0 = pack2(f0.x, f0.x);
            const u64 fa1 = pack2(f0.y, f0.y);
            const u64 fa2 = pack2(f0.z, f0.z);
            const u64 fa3 = pack2(f0.w, f0.w);
            const uint32_t rowa = sboff + (uint32_t)(cc * HALO_H * HALO_W) * 4u;
#pragma unroll
            for (int r = 0; r < 3; r++) {
                const uint32_t a = rowa + (uint32_t)(r * HALO_W) * 4u;
                u64 v0, v1, v2, v3, v4, v5;
                lds128(v0, v1, a);
                lds128(v2, v3, a + 16);
                lds128(v4, v5, a + 32);
                // px0 (cols 4tx+0..8): pairs v0..v3, scalar dj8 = v4.lo
                ffma2(P[r][0][0], fa0, v0); ffma2(P[r][0][1], fa0, v1);
                ffma2(P[r][0][2], fa0, v2); ffma2(P[r][0][3], fa0, v3);
                S[r][0] = fmaf(f0.x, lo32(v4), S[r][0]);
                // px1 (cols 4tx+1..9): scalar dj0 = v0.hi, pairs v1..v4
                ffma2(P[r][1][0], fa1, v1); ffma2(P[r][1][1], fa1, v2);
                ffma2(P[r][1][2], fa1, v3); ffma2(P[r][1][3], fa1, v4);
                S[r][1] = fmaf(f0.y, hi32(v0), S[r][1]);
                // px2 (cols 4tx+2..10): pairs v1..v4, scalar dj8 = v5.lo
                ffma2(P[r][2][0], fa2, v1); ffma2(P[r][2][1], fa2, v2);
                ffma2(P[r][2][2], fa2, v3); ffma2(P[r][2][3], fa2, v4);
                S[r][2] = fmaf(f0.z, lo32(v5), S[r][2]);
                // px3 (cols 4tx+3..11): scalar dj0 = v1.hi, pairs v2..v5
                ffma2(P[r][3][0], fa3, v2); ffma2(P[r][3][1], fa3, v3);
                ffma2(P[r][3][2], fa3, v4); ffma2(P[r][3][3], fa3, v5);
                S[r][3] = fmaf(f0.w, hi32(v1), S[r][3]);
            }
        }

        cur = cur + 1; if (cur >= 3) cur = 0;
    }

    // ---- coalesced output: 4 tile-rows per staging pass (2 passes) ----
#pragma unroll 1
    for (int g = 0; g < 2; g++) {
        __syncthreads();   // pass 0: all compute reads done; pass 1: all copies done
        if ((ty >> 2) == g) {
            float* st = &smem[(size_t)((ty & 3) * TILE_W + 4 * tx) * NSH];
#pragma unroll
            for (int r = 0; r < 3; r++) {
                const int base = (3 * tz + r) * DD;
                float x, y;
#pragma unroll
                for (int p = 0; p < 4; p++) {
                    unpack2(P[r][0][p], x, y);
                    st[0 * NSH + base + 2 * p]     = x;
                    st[0 * NSH + base + 2 * p + 1] = y;
                    unpack2(P[r][1][p], x, y);
                    st[1 * NSH + base + 2 * p + 1] = x;
                    st[1 * NSH + base + 2 * p + 2] = y;
                    unpack2(P[r][2][p], x, y);
                    st[2 * NSH + base + 2 * p]     = x;
                    st[2 * NSH + base + 2 * p + 1] = y;
                    unpack2(P[r][3][p], x, y);
                    st[3 * NSH + base + 2 * p + 1] = x;
                    st[3 * NSH + base + 2 * p + 2] = y;
                }
                st[0 * NSH + base + 8] = S[r][0];
                st[1 * NSH + base + 0] = S[r][1];
                st[2 * NSH + base + 8] = S[r][2];
                st[3 * NSH + base + 0] = S[r][3];
            }
        }
        __syncthreads();
        // copy 4 rows (10368 words) to gmem; out rows stride WW*NSH
        const float4* src = (const float4*)smem;
        for (int i = tid; i < 4 * TILE_W * NSH / 4; i += NTHR) {
            int row = i / (TILE_W * NSH / 4);            // 0..3
            int rem = i - row * (TILE_W * NSH / 4);
            float4* dst = (float4*)(out +
                ((size_t)(b * HH + h0 + 4 * g + row) * WW + w0) * NSH);
            dst[rem] = src[i];
        }
    }
}

extern "C" void kernel_launch(void* const* d_in, const int* in_sizes, int n_in,
                              void* d_out, int out_size)
{
    const float* FM0 = (const float*)d_in[0];
    const float* FM1 = (const float*)d_in[1];
    float* out = (float*)d_out;

    dim3 grid(WW / TILE_W, HH / TILE_H, BATCH);  // (3,12,8) = 288 blocks, 2 CTAs/SM, one wave
    dim3 block(8, TILE_H, 3);                     // 192 threads
    corr_kernel<<<grid, block>>>(FM0, FM1, out);
}